// round 16
// baseline (speedup 1.0000x reference)
#include <cuda_runtime.h>
#include <cuda_bf16.h>
#include <cuda_fp16.h>
#include <stdint.h>
#include <math.h>

#define NN 5000
#define EE 40000
#define EP 45000      // EE + NN self loops
#define HH 8
#define AFS 520       // padded row stride for node-feature buffers

// ---------------- scratch (static device globals; no allocation) ----------------
__device__ float g_af[2][NN * AFS];
__device__ __half g_hb[NN * 4096];       // fp16 GEMM output (aggregation path)
__device__ float g_es[NN * HH];
__device__ float g_ed[NN * HH];
__device__ float g_alpha[EP * HH];
__device__ int   g_cnt[NN];
__device__ int   g_pos[NN];
__device__ int   g_rowptr[NN + 1];
__device__ int   g_srcS[EP];
// split-fp16 operands for tensor-core GEMM (A = Ah + Al, B single fp16)
__device__ __half g_Ah[NN * 528];
__device__ __half g_Al[NN * 528];
__device__ __half g_Bh[1310720];         // max N_pad*K_pad
// folded layer-4 score weights: w~[k,h] = sum_c W4[k, h*20+c] * a{src,dst}4[h,c]
__device__ float g_ws[136 * 8];
__device__ float g_wd[136 * 8];

__device__ __forceinline__ float seluf(float x) {
    const float sc = 1.0507009873554805f, al = 1.6732632423543772f;
    return x > 0.f ? sc * x : sc * al * (expf(x) - 1.f);
}
__device__ __forceinline__ int edge_src(const int* e, int i) { return i < EE ? e[i] : i - EE; }
__device__ __forceinline__ int edge_dst(const int* e, int i) { return i < EE ? e[EE + i] : i - EE; }

__device__ __forceinline__ uint32_t smem_to_u32(const void* p) {
    uint32_t a;
    asm("{ .reg .u64 t; cvta.to.shared.u64 t, %1; cvt.u32.u64 %0, t; }" : "=r"(a) : "l"(p));
    return a;
}
__device__ __forceinline__ void ldmx4(uint32_t* r, uint32_t addr) {
    asm volatile("ldmatrix.sync.aligned.m8n8.x4.shared.b16 {%0,%1,%2,%3}, [%4];"
                 : "=r"(r[0]), "=r"(r[1]), "=r"(r[2]), "=r"(r[3]) : "r"(addr));
}
__device__ __forceinline__ void ldmx2(uint32_t* r, uint32_t addr) {
    asm volatile("ldmatrix.sync.aligned.m8n8.x2.shared.b16 {%0,%1}, [%2];"
                 : "=r"(r[0]), "=r"(r[1]) : "r"(addr));
}
__device__ __forceinline__ void mma16816h(float* c, const uint32_t* a, const uint32_t* b) {
    asm volatile("mma.sync.aligned.m16n8k16.row.col.f32.f16.f16.f32 "
                 "{%0,%1,%2,%3}, {%4,%5,%6,%7}, {%8,%9}, {%0,%1,%2,%3};"
                 : "+f"(c[0]), "+f"(c[1]), "+f"(c[2]), "+f"(c[3])
                 : "r"(a[0]), "r"(a[1]), "r"(a[2]), "r"(a[3]), "r"(b[0]), "r"(b[1]));
}
__device__ __forceinline__ void cpasync16(uint32_t dst, const void* src, bool valid) {
    int sz = valid ? 16 : 0;
    asm volatile("cp.async.cg.shared.global [%0], [%1], 16, %2;"
                 :: "r"(dst), "l"(src), "r"(sz) : "memory");
}
#define CP_COMMIT() asm volatile("cp.async.commit_group;" ::: "memory")
#define CP_WAIT0()  asm volatile("cp.async.wait_group 0;" ::: "memory")
#define CP_WAIT1()  asm volatile("cp.async.wait_group 1;" ::: "memory")

// ---------------- CSR build ----------------
__global__ void k_count(const int* __restrict__ eidx) {
    int i = blockIdx.x * blockDim.x + threadIdx.x;
    if (i < EP) atomicAdd(&g_cnt[edge_dst(eidx, i)], 1);
}
__global__ void k_scan() {
    __shared__ int sh[1024];
    const int CH = 5;
    int t = threadIdx.x, base = t * CH;
    int loc[CH]; int s = 0;
    #pragma unroll
    for (int i = 0; i < CH; i++) {
        int idx = base + i;
        int v = (idx < NN) ? g_cnt[idx] : 0;
        loc[i] = s; s += v;
    }
    sh[t] = s;
    __syncthreads();
    for (int off = 1; off < 1024; off <<= 1) {
        int v = (t >= off) ? sh[t - off] : 0;
        __syncthreads();
        sh[t] += v;
        __syncthreads();
    }
    int excl = sh[t] - s;
    #pragma unroll
    for (int i = 0; i < CH; i++) {
        int idx = base + i;
        if (idx < NN) g_rowptr[idx] = excl + loc[i];
    }
    if (t == 1023) g_rowptr[NN] = sh[1023];
}
__global__ void k_scatter(const int* __restrict__ eidx) {
    int i = blockIdx.x * blockDim.x + threadIdx.x;
    if (i >= EP) return;
    int d = edge_dst(eidx, i);
    int p = atomicAdd(&g_pos[d], 1);
    g_srcS[g_rowptr[d] + p] = edge_src(eidx, i);
}

// ---------------- layer 0 fused with convA for layer-1 GEMM (+ CSR init) ----------------
__global__ void k_layer0f(const float* __restrict__ data, const float* __restrict__ W0,
                          const float* __restrict__ b0) {
    int n = blockIdx.x;
    int c = threadIdx.x;                  // 256
    const int Kp = 272;                   // Kpd[0]
    if (c == 0) { g_cnt[n] = 0; g_pos[n] = 0; }
    __shared__ float d[16];
    if (c < 10) d[c] = data[n * 10 + c];
    __syncthreads();
    float s = b0[c];
    #pragma unroll
    for (int k = 0; k < 10; k++) s = fmaf(d[k], W0[k * 256 + c], s);
    float v = seluf(s);
    g_af[0][n * AFS + 2 + c] = v;
    __half hi = __float2half_rn(v);
    g_Ah[n * Kp + 2 + c] = hi;
    g_Al[n * Kp + 2 + c] = __float2half_rn(v - __half2float(hi));
    if (c < 2) {
        float cv = d[c];
        g_af[0][n * AFS + c] = cv;
        __half chi = __float2half_rn(cv);
        g_Ah[n * Kp + c] = chi;
        g_Al[n * Kp + c] = __float2half_rn(cv - __half2float(chi));
    }
    if (c < 14) {                          // pad [258, 272)
        g_Ah[n * Kp + 258 + c] = __float2half_rn(0.f);
        g_Al[n * Kp + 258 + c] = __float2half_rn(0.f);
    }
}

// ---------------- fold layer-4 weights: w~[k,h] = sum_c W4[k,h*20+c]*a4[h,c] ----------------
__global__ void k_foldW(const float* __restrict__ W4, const float* __restrict__ as4,
                        const float* __restrict__ ad4) {
    int i = blockIdx.x * blockDim.x + threadIdx.x;
    if (i >= 136 * 8) return;
    int k = i >> 3, h = i & 7;
    float ss = 0.f, sd = 0.f;
    #pragma unroll
    for (int c = 0; c < 20; c++) {
        float w = W4[k * 160 + h * 20 + c];
        ss = fmaf(w, as4[h * 20 + c], ss);
        sd = fmaf(w, ad4[h * 20 + c], sd);
    }
    g_ws[i] = ss;
    g_wd[i] = sd;
}

// ---------------- layer-4 scores: es/ed = af4 @ w~ (fp32, K=136) ----------------
__global__ void k_scores4(int sel) {
    __shared__ float saf[32 * 136];
    int n0 = blockIdx.x * 32;
    const float* af = g_af[sel];
    for (int idx = threadIdx.x; idx < 32 * 136; idx += 256) {
        int r = idx / 136, c = idx - r * 136;
        int n = n0 + r;
        saf[idx] = (n < NN) ? af[n * AFS + c] : 0.f;
    }
    __syncthreads();
    int r = threadIdx.x >> 3, h = threadIdx.x & 7;
    int n = n0 + r;
    if (n < NN) {
        const float* a = &saf[r * 136];
        float ss = 0.f, sd = 0.f;
        #pragma unroll 8
        for (int k = 0; k < 136; k++) {
            float v = a[k];
            ss = fmaf(v, g_ws[k * 8 + h], ss);
            sd = fmaf(v, g_wd[k * 8 + h], sd);
        }
        g_es[n * HH + h] = ss;
        g_ed[n * HH + h] = sd;
    }
}

// ---------------- B conversion (also zeroes es/ed for the following GEMM) ----------------
__global__ void k_convB(const float* __restrict__ W, int K, int Ncols, int Kp, int Npad) {
    int gid = ((blockIdx.y * gridDim.x + blockIdx.x) * 8 + threadIdx.y) * 32 + threadIdx.x;
    if (gid < NN * HH) { g_es[gid] = 0.f; g_ed[gid] = 0.f; }
    __shared__ float sh[32][33];
    int k0 = blockIdx.x * 32, n0 = blockIdx.y * 32;
    int tx = threadIdx.x, ty = threadIdx.y;      // (32, 8)
    #pragma unroll
    for (int i = 0; i < 4; i++) {
        int k = k0 + ty + 8 * i, n = n0 + tx;
        sh[ty + 8 * i][tx] = (k < K && n < Ncols) ? W[k * Ncols + n] : 0.f;
    }
    __syncthreads();
    #pragma unroll
    for (int i = 0; i < 4; i++) {
        int n = n0 + ty + 8 * i, k = k0 + tx;
        if (k < Kp && n < Npad)
            g_Bh[(size_t)n * Kp + k] = __float2half_rn(sh[tx][ty + 8 * i]);
    }
}

// ---------------- 3-stage cp.async mma.sync fp16x2 GEMM (fused score epilogue) ----------------
#define BM 128
#define BN 128
#define BK 16
#define ASTR 24
#define ARR_B (BM * ASTR * 2)
#define STG_B (3 * ARR_B)
#define NSTG 3
#define SMEM_MMA (NSTG * STG_B)

__global__ void __launch_bounds__(256, 2) k_mma_sync(int Kp, int M, int Nc,
                                                     const float* __restrict__ asrc,
                                                     const float* __restrict__ adst) {
    extern __shared__ char smem[];
    const uint32_t sb = smem_to_u32(smem);

    const int tid = threadIdx.x, lane = tid & 31, wid = tid >> 5;
    const int warp_m = wid >> 2, warp_n = wid & 3;
    const int bm = blockIdx.y * BM, bn = blockIdx.x * BN;

    const int lr = tid >> 1;
    const int lc = (tid & 1) * 16;
    const int col8 = (tid & 1) * 8;

    const int a_row = lane & 15, a_hi = lane >> 4;
    const int b_row = lane & 7,  b_hi = (lane >> 3) & 1;

    float acc[4][4][4];
    #pragma unroll
    for (int i = 0; i < 4; i++)
        #pragma unroll
        for (int j = 0; j < 4; j++)
            #pragma unroll
            for (int t = 0; t < 4; t++) acc[i][j][t] = 0.f;

    const int nblk = Kp / BK;

    auto load_stage = [&](int st, int k0) {
        uint32_t s0 = sb + st * STG_B;
        int gr = bm + lr;
        int cr = gr < M ? gr : 0;
        cpasync16(s0 + 0 * ARR_B + lr * 48 + lc, &g_Ah[(size_t)cr * Kp + k0 + col8], gr < M);
        cpasync16(s0 + 1 * ARR_B + lr * 48 + lc, &g_Al[(size_t)cr * Kp + k0 + col8], gr < M);
        int gn = bn + lr;
        cpasync16(s0 + 2 * ARR_B + lr * 48 + lc, &g_Bh[(size_t)gn * Kp + k0 + col8], true);
    };

    load_stage(0, 0);
    CP_COMMIT();
    if (nblk > 1) { load_stage(1, BK); CP_COMMIT(); }

    int stage = 0;
    for (int blk = 0; blk < nblk; blk++) {
        if (blk + 1 < nblk) { CP_WAIT1(); } else { CP_WAIT0(); }
        __syncthreads();
        if (blk + 2 < nblk) {
            int nst = stage + 2; if (nst >= NSTG) nst -= NSTG;
            load_stage(nst, (blk + 2) * BK);
            CP_COMMIT();
        }
        const uint32_t st = sb + stage * STG_B;
        const uint32_t bAh = st, bAl = st + ARR_B, bB = st + 2 * ARR_B;

        uint32_t bh[4][2];
        #pragma unroll
        for (int j = 0; j < 4; j++) {
            uint32_t off = (uint32_t)(((warp_n * 32 + j * 8 + b_row) * ASTR + b_hi * 8) * 2);
            ldmx2(bh[j], bB + off);
        }
        #pragma unroll
        for (int i = 0; i < 4; i++) {
            uint32_t ah[4], al[4];
            uint32_t off = (uint32_t)(((warp_m * 64 + i * 16 + a_row) * ASTR + a_hi * 8) * 2);
            ldmx4(ah, bAh + off);
            ldmx4(al, bAl + off);
            #pragma unroll
            for (int j = 0; j < 4; j++) {
                mma16816h(acc[i][j], ah, bh[j]);
                mma16816h(acc[i][j], al, bh[j]);
            }
        }
        if (++stage >= NSTG) stage = 0;
    }

    // fp16 store + fused attention scores (Nc == Npad, C >= 128 for layers 1-3)
    const int Cw = Nc / HH;
    const int head = (bn + warp_n * 32) / Cw;
    float2 asv[4], adv[4];
    #pragma unroll
    for (int j = 0; j < 4; j++) {
        int n0 = bn + warp_n * 32 + j * 8 + (lane & 3) * 2;
        asv[j] = *(const float2*)&asrc[n0];
        adv[j] = *(const float2*)&adst[n0];
    }
    #pragma unroll
    for (int i = 0; i < 4; i++) {
        int m0 = bm + warp_m * 64 + i * 16 + (lane >> 2);
        int m1 = m0 + 8;
        float ps0 = 0.f, pd0 = 0.f, ps1 = 0.f, pd1 = 0.f;
        #pragma unroll
        for (int j = 0; j < 4; j++) {
            int n0 = bn + warp_n * 32 + j * 8 + (lane & 3) * 2;
            ps0 += acc[i][j][0] * asv[j].x + acc[i][j][1] * asv[j].y;
            pd0 += acc[i][j][0] * adv[j].x + acc[i][j][1] * adv[j].y;
            ps1 += acc[i][j][2] * asv[j].x + acc[i][j][3] * asv[j].y;
            pd1 += acc[i][j][2] * adv[j].x + acc[i][j][3] * adv[j].y;
            if (m0 < M)
                *(__half2*)&g_hb[(size_t)m0 * Nc + n0] =
                    __floats2half2_rn(acc[i][j][0], acc[i][j][1]);
            if (m1 < M)
                *(__half2*)&g_hb[(size_t)m1 * Nc + n0] =
                    __floats2half2_rn(acc[i][j][2], acc[i][j][3]);
        }
        ps0 += __shfl_xor_sync(0xFFFFFFFFu, ps0, 1); ps0 += __shfl_xor_sync(0xFFFFFFFFu, ps0, 2);
        pd0 += __shfl_xor_sync(0xFFFFFFFFu, pd0, 1); pd0 += __shfl_xor_sync(0xFFFFFFFFu, pd0, 2);
        ps1 += __shfl_xor_sync(0xFFFFFFFFu, ps1, 1); ps1 += __shfl_xor_sync(0xFFFFFFFFu, ps1, 2);
        pd1 += __shfl_xor_sync(0xFFFFFFFFu, pd1, 1); pd1 += __shfl_xor_sync(0xFFFFFFFFu, pd1, 2);
        if ((lane & 3) == 0) {
            if (m0 < M) {
                atomicAdd(&g_es[m0 * HH + head], ps0);
                atomicAdd(&g_ed[m0 * HH + head], pd0);
            }
            if (m1 < M) {
                atomicAdd(&g_es[m1 * HH + head], ps1);
                atomicAdd(&g_ed[m1 * HH + head], pd1);
            }
        }
    }
}

// ---------------- edge softmax (all layers) ----------------
__global__ void k_softmax() {
    int warp = (blockIdx.x * blockDim.x + threadIdx.x) >> 5;
    if (warp >= NN) return;
    int lane = threadIdx.x & 31;
    int n = warp;
    int beg = g_rowptr[n], end = g_rowptr[n + 1];
    int el = lane >> 3;
    int hh = lane & 7;
    float edv = g_ed[n * HH + hh];

    float mx = -INFINITY;
    for (int s = beg; s < end; s += 4) {
        int si = s + el;
        float lg = -INFINITY;
        if (si < end) {
            float x = g_es[g_srcS[si] * HH + hh] + edv;
            lg = x >= 0.f ? x : 0.2f * x;
        }
        mx = fmaxf(mx, lg);
    }
    mx = fmaxf(mx, __shfl_xor_sync(0xFFFFFFFFu, mx, 8));
    mx = fmaxf(mx, __shfl_xor_sync(0xFFFFFFFFu, mx, 16));

    float se = 0.f;
    for (int s = beg; s < end; s += 4) {
        int si = s + el;
        if (si < end) {
            float x = g_es[g_srcS[si] * HH + hh] + edv;
            x = x >= 0.f ? x : 0.2f * x;
            se += expf(x - mx);
        }
    }
    se += __shfl_xor_sync(0xFFFFFFFFu, se, 8);
    se += __shfl_xor_sync(0xFFFFFFFFu, se, 16);
    float inv = 1.f / se;

    for (int s = beg; s < end; s += 4) {
        int si = s + el;
        if (si < end) {
            float x = g_es[g_srcS[si] * HH + hh] + edv;
            x = x >= 0.f ? x : 0.2f * x;
            g_alpha[si * HH + hh] = expf(x - mx) * inv;
        }
    }
}

// ---------------- aggregation (fp16 h, global alpha) + coord + convA epilogue ----------------
__global__ void k_aggf(int sel, const float* __restrict__ bias, int C, int copyw,
                       int Kp_next) {
    int n = blockIdx.x;
    int tid = threadIdx.x;   // 128
    const float* af_in = g_af[sel];
    float* af_out = g_af[sel ^ 1];
    int beg = g_rowptr[n], end = g_rowptr[n + 1];
    const int P = C >> 1;
    float2 acc2[2] = {{0.f, 0.f}, {0.f, 0.f}};
    float oc0 = 0.f, oc1 = 0.f;

    for (int s = beg; s < end; s++) {
        int sn = g_srcS[s];
        const __half* hr = g_hb + (size_t)sn * (HH * C);
        const float* ar = g_alpha + (size_t)s * HH;
        float a[HH];
        #pragma unroll
        for (int h = 0; h < HH; h++) a[h] = ar[h];
        #pragma unroll
        for (int r = 0; r < 2; r++) {
            int p = tid + r * 128;
            if (p < P) {
                float vx = 0.f, vy = 0.f;
                #pragma unroll
                for (int h = 0; h < HH; h++) {
                    __half2 hv = *(const __half2*)&hr[h * C + 2 * p];
                    float2 f = __half22float2(hv);
                    vx = fmaf(a[h], f.x, vx);
                    vy = fmaf(a[h], f.y, vy);
                }
                acc2[r].x += vx;
                acc2[r].y += vy;
            }
        }
        if (tid == 0) {
            float sa = 0.f;
            #pragma unroll
            for (int h = 0; h < HH; h++) sa += a[h];
            oc0 = fmaf(sa, af_in[sn * AFS + 0], oc0);
            oc1 = fmaf(sa, af_in[sn * AFS + 1], oc1);
        }
    }

    // epilogue: af_out (+ split-fp16 A operands when another GEMM follows)
    const int Kn = 2 + copyw + C;
    __half* Ah = g_Ah + (size_t)n * Kp_next;
    __half* Al = g_Al + (size_t)n * Kp_next;
    #pragma unroll
    for (int r = 0; r < 2; r++) {
        int p = tid + r * 128;
        if (p < P) {
            int c = 2 * p;
            float v0 = seluf(acc2[r].x * 0.125f + bias[c]);
            float v1 = seluf(acc2[r].y * 0.125f + bias[c + 1]);
            int k0 = 2 + copyw + c;
            af_out[n * AFS + k0] = v0;
            af_out[n * AFS + k0 + 1] = v1;
            if (Kp_next) {
                __half h0 = __float2half_rn(v0), h1 = __float2half_rn(v1);
                *(__half2*)&Ah[k0] = __halves2half2(h0, h1);
                *(__half2*)&Al[k0] = __halves2half2(__float2half_rn(v0 - __half2float(h0)),
                                                    __float2half_rn(v1 - __half2float(h1)));
            }
        }
    }
    if (tid < copyw) {
        float v = af_in[n * AFS + tid];
        af_out[n * AFS + 2 + tid] = v;
        if (Kp_next) {
            __half hv = __float2half_rn(v);
            Ah[2 + tid] = hv;
            Al[2 + tid] = __float2half_rn(v - __half2float(hv));
        }
    }
    if (tid < Kp_next - Kn) {
        Ah[Kn + tid] = __float2half_rn(0.f);
        Al[Kn + tid] = __float2half_rn(0.f);
    }
    if (tid == 0) {
        float a0 = af_in[n * AFS + 0], a1 = af_in[n * AFS + 1];
        float c0 = (a0 == 0.f) ? 0.f : ((a0 == 1.f) ? 1.f : oc0 * (0.2f * 0.125f));
        float c1 = (a1 == 1.f) ? 1.f : ((a1 == 0.f) ? 0.f : oc1 * (0.2f * 0.125f));
        af_out[n * AFS + 0] = c0;
        af_out[n * AFS + 1] = c1;
        if (Kp_next) {
            __half h0 = __float2half_rn(c0), h1 = __float2half_rn(c1);
            *(__half2*)&Ah[0] = __halves2half2(h0, h1);
            *(__half2*)&Al[0] = __halves2half2(__float2half_rn(c0 - __half2float(h0)),
                                               __float2half_rn(c1 - __half2float(h1)));
        }
    }
}

// ---------------- final layer ----------------
__global__ void k_final(int sel, float* __restrict__ out) {
    int n = blockIdx.x;
    int lane = threadIdx.x;
    const float* af_in = g_af[sel];
    int beg = g_rowptr[n], end = g_rowptr[n + 1];
    float oc0 = 0.f, oc1 = 0.f;
    for (int s = beg + lane; s < end; s += 32) {
        int sn = g_srcS[s];
        float sa = 0.f;
        #pragma unroll
        for (int h = 0; h < HH; h++) sa += g_alpha[s * HH + h];
        oc0 = fmaf(sa, af_in[sn * AFS + 0], oc0);
        oc1 = fmaf(sa, af_in[sn * AFS + 1], oc1);
    }
    #pragma unroll
    for (int off = 16; off > 0; off >>= 1) {
        oc0 += __shfl_xor_sync(0xFFFFFFFFu, oc0, off);
        oc1 += __shfl_xor_sync(0xFFFFFFFFu, oc1, off);
    }
    if (lane == 0) {
        float a0 = af_in[n * AFS + 0], a1 = af_in[n * AFS + 1];
        float c0 = (a0 == 0.f) ? 0.f : ((a0 == 1.f) ? 1.f : oc0 * (0.2f * 0.125f));
        float c1 = (a1 == 1.f) ? 1.f : ((a1 == 0.f) ? 0.f : oc1 * (0.2f * 0.125f));
        out[n * 2 + 0] = c0;
        out[n * 2 + 1] = c1;
    }
}

// ---------------- launch ----------------
extern "C" void kernel_launch(void* const* d_in, const int* in_sizes, int n_in,
                              void* d_out, int out_size) {
    const float* data = (const float*)d_in[0];
    const int* eidx = (const int*)d_in[1];
    const float* W0 = (const float*)d_in[2];
    const float* b0 = (const float*)d_in[3];
    const float *W[4], *As[4], *Ad[4], *Bi[4];
    for (int i = 0; i < 4; i++) {
        W[i]  = (const float*)d_in[4 + 4 * i];
        As[i] = (const float*)d_in[5 + 4 * i];
        Ad[i] = (const float*)d_in[6 + 4 * i];
        Bi[i] = (const float*)d_in[7 + 4 * i];
    }
    float* out = (float*)d_out;

    cudaFuncSetAttribute(k_mma_sync, cudaFuncAttributeMaxDynamicSharedMemorySize, SMEM_MMA);

    const int Kd[4]  = {258, 516, 262, 136};
    const int Kpd[4] = {272, 528, 272, 144};
    const int Cd[4]  = {512, 256, 128, 20};

    // layer0 (+convA1 +CSR-init), convB1, foldW, then GEMM1 in the ncu capture slot
    k_layer0f<<<NN, 256>>>(data, W0, b0);
    {
        int Npad = HH * Cd[0];
        dim3 gb((Kpd[0] + 31) / 32, Npad / 32);
        k_convB<<<gb, dim3(32, 8)>>>(W[0], Kd[0], HH * Cd[0], Kpd[0], Npad);
    }
    k_foldW<<<5, 256>>>(W[3], As[3], Ad[3]);
    {
        int Npad = HH * Cd[0];
        dim3 gg(Npad / 128, (NN + 127) / 128);
        k_mma_sync<<<gg, 256, SMEM_MMA>>>(Kpd[0], NN, HH * Cd[0], As[0], Ad[0]);
    }
    k_count<<<(EP + 255) / 256, 256>>>(eidx);
    k_scan<<<1, 1024>>>();
    k_scatter<<<(EP + 255) / 256, 256>>>(eidx);

    int sel = 0;
    for (int l = 0; l < 3; l++) {
        int Nc = HH * Cd[l];
        int Kp = Kpd[l];
        if (l > 0) {
            dim3 gb((Kp + 31) / 32, Nc / 32);
            k_convB<<<gb, dim3(32, 8)>>>(W[l], Kd[l], Nc, Kp, Nc);
            dim3 gg(Nc / 128, (NN + 127) / 128);
            k_mma_sync<<<gg, 256, SMEM_MMA>>>(Kp, NN, Nc, As[l], Ad[l]);
        }
        k_softmax<<<(NN + 7) / 8, 256>>>();
        int Kp_next = (l < 2) ? Kpd[l + 1] : 0;   // no GEMM after layer-3 aggregation
        k_aggf<<<NN, 128>>>(sel, Bi[l], Cd[l], 2 * l + 2, Kp_next);
        sel ^= 1;
    }
    // layer 4: folded scores -> softmax -> coords
    k_scores4<<<(NN + 31) / 32, 256>>>(sel);
    k_softmax<<<(NN + 7) / 8, 256>>>();
    k_final<<<NN, 32>>>(sel, out);
}

// round 17
// speedup vs baseline: 1.1877x; 1.1877x over previous
#include <cuda_runtime.h>
#include <cuda_bf16.h>
#include <cuda_fp16.h>
#include <stdint.h>
#include <math.h>

#define NN 5000
#define EE 40000
#define EP 45000      // EE + NN self loops
#define HH 8
#define AFS 520       // padded row stride for node-feature buffers

// ---------------- scratch (static device globals; no allocation) ----------------
__device__ float g_af[2][NN * AFS];
__device__ __half g_hb[NN * 4096];       // fp16 GEMM output (aggregation path)
__device__ float g_es[NN * HH];
__device__ float g_ed[NN * HH];
__device__ float g_alpha[EP * HH];
__device__ int   g_cnt[NN];
__device__ int   g_pos[NN];
__device__ int   g_rowptr[NN + 1];
__device__ int   g_srcS[EP];
// fp16 operands for tensor-core GEMM (single-term: h = fp16(A) @ fp16(B)^T)
__device__ __half g_Ah[NN * 528];
__device__ __half g_Bh[1310720];         // max N_pad*K_pad
// folded layer-4 score weights
__device__ float g_ws[136 * 8];
__device__ float g_wd[136 * 8];

__device__ __forceinline__ float seluf(float x) {
    const float sc = 1.0507009873554805f, al = 1.6732632423543772f;
    return x > 0.f ? sc * x : sc * al * (expf(x) - 1.f);
}
__device__ __forceinline__ int edge_src(const int* e, int i) { return i < EE ? e[i] : i - EE; }
__device__ __forceinline__ int edge_dst(const int* e, int i) { return i < EE ? e[EE + i] : i - EE; }

__device__ __forceinline__ uint32_t smem_to_u32(const void* p) {
    uint32_t a;
    asm("{ .reg .u64 t; cvta.to.shared.u64 t, %1; cvt.u32.u64 %0, t; }" : "=r"(a) : "l"(p));
    return a;
}
__device__ __forceinline__ void ldmx4(uint32_t* r, uint32_t addr) {
    asm volatile("ldmatrix.sync.aligned.m8n8.x4.shared.b16 {%0,%1,%2,%3}, [%4];"
                 : "=r"(r[0]), "=r"(r[1]), "=r"(r[2]), "=r"(r[3]) : "r"(addr));
}
__device__ __forceinline__ void ldmx2(uint32_t* r, uint32_t addr) {
    asm volatile("ldmatrix.sync.aligned.m8n8.x2.shared.b16 {%0,%1}, [%2];"
                 : "=r"(r[0]), "=r"(r[1]) : "r"(addr));
}
__device__ __forceinline__ void mma16816h(float* c, const uint32_t* a, const uint32_t* b) {
    asm volatile("mma.sync.aligned.m16n8k16.row.col.f32.f16.f16.f32 "
                 "{%0,%1,%2,%3}, {%4,%5,%6,%7}, {%8,%9}, {%0,%1,%2,%3};"
                 : "+f"(c[0]), "+f"(c[1]), "+f"(c[2]), "+f"(c[3])
                 : "r"(a[0]), "r"(a[1]), "r"(a[2]), "r"(a[3]), "r"(b[0]), "r"(b[1]));
}
__device__ __forceinline__ void cpasync16(uint32_t dst, const void* src, bool valid) {
    int sz = valid ? 16 : 0;
    asm volatile("cp.async.cg.shared.global [%0], [%1], 16, %2;"
                 :: "r"(dst), "l"(src), "r"(sz) : "memory");
}
#define CP_COMMIT() asm volatile("cp.async.commit_group;" ::: "memory")
#define CP_WAIT0()  asm volatile("cp.async.wait_group 0;" ::: "memory")
#define CP_WAIT1()  asm volatile("cp.async.wait_group 1;" ::: "memory")

// ---------------- CSR build ----------------
__global__ void k_count(const int* __restrict__ eidx) {
    int i = blockIdx.x * blockDim.x + threadIdx.x;
    if (i < EP) atomicAdd(&g_cnt[edge_dst(eidx, i)], 1);
}
__global__ void k_scan() {
    __shared__ int sh[1024];
    const int CH = 5;
    int t = threadIdx.x, base = t * CH;
    int loc[CH]; int s = 0;
    #pragma unroll
    for (int i = 0; i < CH; i++) {
        int idx = base + i;
        int v = (idx < NN) ? g_cnt[idx] : 0;
        loc[i] = s; s += v;
    }
    sh[t] = s;
    __syncthreads();
    for (int off = 1; off < 1024; off <<= 1) {
        int v = (t >= off) ? sh[t - off] : 0;
        __syncthreads();
        sh[t] += v;
        __syncthreads();
    }
    int excl = sh[t] - s;
    #pragma unroll
    for (int i = 0; i < CH; i++) {
        int idx = base + i;
        if (idx < NN) g_rowptr[idx] = excl + loc[i];
    }
    if (t == 1023) g_rowptr[NN] = sh[1023];
}
__global__ void k_scatter(const int* __restrict__ eidx) {
    int i = blockIdx.x * blockDim.x + threadIdx.x;
    if (i >= EP) return;
    int d = edge_dst(eidx, i);
    int p = atomicAdd(&g_pos[d], 1);
    g_srcS[g_rowptr[d] + p] = edge_src(eidx, i);
}

// ---------------- layer 0 fused with convA for layer-1 GEMM (+ CSR init) ----------------
__global__ void k_layer0f(const float* __restrict__ data, const float* __restrict__ W0,
                          const float* __restrict__ b0) {
    int n = blockIdx.x;
    int c = threadIdx.x;                  // 256
    const int Kp = 272;                   // Kpd[0]
    if (c == 0) { g_cnt[n] = 0; g_pos[n] = 0; }
    __shared__ float d[16];
    if (c < 10) d[c] = data[n * 10 + c];
    __syncthreads();
    float s = b0[c];
    #pragma unroll
    for (int k = 0; k < 10; k++) s = fmaf(d[k], W0[k * 256 + c], s);
    float v = seluf(s);
    g_af[0][n * AFS + 2 + c] = v;
    g_Ah[n * Kp + 2 + c] = __float2half_rn(v);
    if (c < 2) {
        float cv = d[c];
        g_af[0][n * AFS + c] = cv;
        g_Ah[n * Kp + c] = __float2half_rn(cv);
    }
    if (c < 14)                            // pad [258, 272)
        g_Ah[n * Kp + 258 + c] = __float2half_rn(0.f);
}

// ---------------- fold layer-4 weights ----------------
__global__ void k_foldW(const float* __restrict__ W4, const float* __restrict__ as4,
                        const float* __restrict__ ad4) {
    int i = blockIdx.x * blockDim.x + threadIdx.x;
    if (i >= 136 * 8) return;
    int k = i >> 3, h = i & 7;
    float ss = 0.f, sd = 0.f;
    #pragma unroll
    for (int c = 0; c < 20; c++) {
        float w = W4[k * 160 + h * 20 + c];
        ss = fmaf(w, as4[h * 20 + c], ss);
        sd = fmaf(w, ad4[h * 20 + c], sd);
    }
    g_ws[i] = ss;
    g_wd[i] = sd;
}

// ---------------- layer-4 scores: es/ed = af4 @ w~ (fp32, K=136) ----------------
__global__ void k_scores4(int sel) {
    __shared__ float saf[32 * 136];
    int n0 = blockIdx.x * 32;
    const float* af = g_af[sel];
    for (int idx = threadIdx.x; idx < 32 * 136; idx += 256) {
        int r = idx / 136, c = idx - r * 136;
        int n = n0 + r;
        saf[idx] = (n < NN) ? af[n * AFS + c] : 0.f;
    }
    __syncthreads();
    int r = threadIdx.x >> 3, h = threadIdx.x & 7;
    int n = n0 + r;
    if (n < NN) {
        const float* a = &saf[r * 136];
        float ss = 0.f, sd = 0.f;
        #pragma unroll 8
        for (int k = 0; k < 136; k++) {
            float v = a[k];
            ss = fmaf(v, g_ws[k * 8 + h], ss);
            sd = fmaf(v, g_wd[k * 8 + h], sd);
        }
        g_es[n * HH + h] = ss;
        g_ed[n * HH + h] = sd;
    }
}

// ---------------- B conversion (also zeroes es/ed for the following GEMM) ----------------
__global__ void k_convB(const float* __restrict__ W, int K, int Ncols, int Kp, int Npad) {
    int gid = ((blockIdx.y * gridDim.x + blockIdx.x) * 8 + threadIdx.y) * 32 + threadIdx.x;
    if (gid < NN * HH) { g_es[gid] = 0.f; g_ed[gid] = 0.f; }
    __shared__ float sh[32][33];
    int k0 = blockIdx.x * 32, n0 = blockIdx.y * 32;
    int tx = threadIdx.x, ty = threadIdx.y;      // (32, 8)
    #pragma unroll
    for (int i = 0; i < 4; i++) {
        int k = k0 + ty + 8 * i, n = n0 + tx;
        sh[ty + 8 * i][tx] = (k < K && n < Ncols) ? W[k * Ncols + n] : 0.f;
    }
    __syncthreads();
    #pragma unroll
    for (int i = 0; i < 4; i++) {
        int n = n0 + ty + 8 * i, k = k0 + tx;
        if (k < Kp && n < Npad)
            g_Bh[(size_t)n * Kp + k] = __float2half_rn(sh[tx][ty + 8 * i]);
    }
}

// ---------------- 3-stage cp.async mma.sync fp16 GEMM (single-term, fused scores) ----------------
#define BM 128
#define BN 128
#define BK 16
#define ASTR 24
#define ARR_B (BM * ASTR * 2)         // 6144 bytes per operand array
#define STG_B (2 * ARR_B)             // 12288 bytes per stage (Ah, B)
#define NSTG 3
#define SMEM_MMA (NSTG * STG_B)       // 36864 bytes

__global__ void __launch_bounds__(256, 2) k_mma_sync(int Kp, int M, int Nc,
                                                     const float* __restrict__ asrc,
                                                     const float* __restrict__ adst) {
    extern __shared__ char smem[];
    const uint32_t sb = smem_to_u32(smem);

    const int tid = threadIdx.x, lane = tid & 31, wid = tid >> 5;
    const int warp_m = wid >> 2, warp_n = wid & 3;
    const int bm = blockIdx.y * BM, bn = blockIdx.x * BN;

    const int lr = tid >> 1;
    const int lc = (tid & 1) * 16;
    const int col8 = (tid & 1) * 8;

    const int a_row = lane & 15, a_hi = lane >> 4;
    const int b_row = lane & 7,  b_hi = (lane >> 3) & 1;

    float acc[4][4][4];
    #pragma unroll
    for (int i = 0; i < 4; i++)
        #pragma unroll
        for (int j = 0; j < 4; j++)
            #pragma unroll
            for (int t = 0; t < 4; t++) acc[i][j][t] = 0.f;

    const int nblk = Kp / BK;

    auto load_stage = [&](int st, int k0) {
        uint32_t s0 = sb + st * STG_B;
        int gr = bm + lr;
        int cr = gr < M ? gr : 0;
        cpasync16(s0 + 0 * ARR_B + lr * 48 + lc, &g_Ah[(size_t)cr * Kp + k0 + col8], gr < M);
        int gn = bn + lr;
        cpasync16(s0 + 1 * ARR_B + lr * 48 + lc, &g_Bh[(size_t)gn * Kp + k0 + col8], true);
    };

    load_stage(0, 0);
    CP_COMMIT();
    if (nblk > 1) { load_stage(1, BK); CP_COMMIT(); }

    int stage = 0;
    for (int blk = 0; blk < nblk; blk++) {
        if (blk + 1 < nblk) { CP_WAIT1(); } else { CP_WAIT0(); }
        __syncthreads();
        if (blk + 2 < nblk) {
            int nst = stage + 2; if (nst >= NSTG) nst -= NSTG;
            load_stage(nst, (blk + 2) * BK);
            CP_COMMIT();
        }
        const uint32_t st = sb + stage * STG_B;
        const uint32_t bAh = st, bB = st + ARR_B;

        uint32_t bh[4][2];
        #pragma unroll
        for (int j = 0; j < 4; j++) {
            uint32_t off = (uint32_t)(((warp_n * 32 + j * 8 + b_row) * ASTR + b_hi * 8) * 2);
            ldmx2(bh[j], bB + off);
        }
        #pragma unroll
        for (int i = 0; i < 4; i++) {
            uint32_t ah[4];
            uint32_t off = (uint32_t)(((warp_m * 64 + i * 16 + a_row) * ASTR + a_hi * 8) * 2);
            ldmx4(ah, bAh + off);
            #pragma unroll
            for (int j = 0; j < 4; j++)
                mma16816h(acc[i][j], ah, bh[j]);
        }
        if (++stage >= NSTG) stage = 0;
    }

    // fp16 store + fused attention scores (Nc == Npad, C >= 128 for layers 1-3)
    const int Cw = Nc / HH;
    const int head = (bn + warp_n * 32) / Cw;
    float2 asv[4], adv[4];
    #pragma unroll
    for (int j = 0; j < 4; j++) {
        int n0 = bn + warp_n * 32 + j * 8 + (lane & 3) * 2;
        asv[j] = *(const float2*)&asrc[n0];
        adv[j] = *(const float2*)&adst[n0];
    }
    #pragma unroll
    for (int i = 0; i < 4; i++) {
        int m0 = bm + warp_m * 64 + i * 16 + (lane >> 2);
        int m1 = m0 + 8;
        float ps0 = 0.f, pd0 = 0.f, ps1 = 0.f, pd1 = 0.f;
        #pragma unroll
        for (int j = 0; j < 4; j++) {
            int n0 = bn + warp_n * 32 + j * 8 + (lane & 3) * 2;
            ps0 += acc[i][j][0] * asv[j].x + acc[i][j][1] * asv[j].y;
            pd0 += acc[i][j][0] * adv[j].x + acc[i][j][1] * adv[j].y;
            ps1 += acc[i][j][2] * asv[j].x + acc[i][j][3] * asv[j].y;
            pd1 += acc[i][j][2] * adv[j].x + acc[i][j][3] * adv[j].y;
            if (m0 < M)
                *(__half2*)&g_hb[(size_t)m0 * Nc + n0] =
                    __floats2half2_rn(acc[i][j][0], acc[i][j][1]);
            if (m1 < M)
                *(__half2*)&g_hb[(size_t)m1 * Nc + n0] =
                    __floats2half2_rn(acc[i][j][2], acc[i][j][3]);
        }
        ps0 += __shfl_xor_sync(0xFFFFFFFFu, ps0, 1); ps0 += __shfl_xor_sync(0xFFFFFFFFu, ps0, 2);
        pd0 += __shfl_xor_sync(0xFFFFFFFFu, pd0, 1); pd0 += __shfl_xor_sync(0xFFFFFFFFu, pd0, 2);
        ps1 += __shfl_xor_sync(0xFFFFFFFFu, ps1, 1); ps1 += __shfl_xor_sync(0xFFFFFFFFu, ps1, 2);
        pd1 += __shfl_xor_sync(0xFFFFFFFFu, pd1, 1); pd1 += __shfl_xor_sync(0xFFFFFFFFu, pd1, 2);
        if ((lane & 3) == 0) {
            if (m0 < M) {
                atomicAdd(&g_es[m0 * HH + head], ps0);
                atomicAdd(&g_ed[m0 * HH + head], pd0);
            }
            if (m1 < M) {
                atomicAdd(&g_es[m1 * HH + head], ps1);
                atomicAdd(&g_ed[m1 * HH + head], pd1);
            }
        }
    }
}

// ---------------- edge softmax (all layers) ----------------
__global__ void k_softmax() {
    int warp = (blockIdx.x * blockDim.x + threadIdx.x) >> 5;
    if (warp >= NN) return;
    int lane = threadIdx.x & 31;
    int n = warp;
    int beg = g_rowptr[n], end = g_rowptr[n + 1];
    int el = lane >> 3;
    int hh = lane & 7;
    float edv = g_ed[n * HH + hh];

    float mx = -INFINITY;
    for (int s = beg; s < end; s += 4) {
        int si = s + el;
        float lg = -INFINITY;
        if (si < end) {
            float x = g_es[g_srcS[si] * HH + hh] + edv;
            lg = x >= 0.f ? x : 0.2f * x;
        }
        mx = fmaxf(mx, lg);
    }
    mx = fmaxf(mx, __shfl_xor_sync(0xFFFFFFFFu, mx, 8));
    mx = fmaxf(mx, __shfl_xor_sync(0xFFFFFFFFu, mx, 16));

    float se = 0.f;
    for (int s = beg; s < end; s += 4) {
        int si = s + el;
        if (si < end) {
            float x = g_es[g_srcS[si] * HH + hh] + edv;
            x = x >= 0.f ? x : 0.2f * x;
            se += expf(x - mx);
        }
    }
    se += __shfl_xor_sync(0xFFFFFFFFu, se, 8);
    se += __shfl_xor_sync(0xFFFFFFFFu, se, 16);
    float inv = 1.f / se;

    for (int s = beg; s < end; s += 4) {
        int si = s + el;
        if (si < end) {
            float x = g_es[g_srcS[si] * HH + hh] + edv;
            x = x >= 0.f ? x : 0.2f * x;
            g_alpha[si * HH + hh] = expf(x - mx) * inv;
        }
    }
}

// ---------------- aggregation (fp16 h, global alpha) + coord + convA epilogue ----------------
__global__ void k_aggf(int sel, const float* __restrict__ bias, int C, int copyw,
                       int Kp_next) {
    int n = blockIdx.x;
    int tid = threadIdx.x;   // 128
    const float* af_in = g_af[sel];
    float* af_out = g_af[sel ^ 1];
    int beg = g_rowptr[n], end = g_rowptr[n + 1];
    const int P = C >> 1;
    float2 acc2[2] = {{0.f, 0.f}, {0.f, 0.f}};
    float oc0 = 0.f, oc1 = 0.f;

    for (int s = beg; s < end; s++) {
        int sn = g_srcS[s];
        const __half* hr = g_hb + (size_t)sn * (HH * C);
        const float* ar = g_alpha + (size_t)s * HH;
        float a[HH];
        #pragma unroll
        for (int h = 0; h < HH; h++) a[h] = ar[h];
        #pragma unroll
        for (int r = 0; r < 2; r++) {
            int p = tid + r * 128;
            if (p < P) {
                float vx = 0.f, vy = 0.f;
                #pragma unroll
                for (int h = 0; h < HH; h++) {
                    __half2 hv = *(const __half2*)&hr[h * C + 2 * p];
                    float2 f = __half22float2(hv);
                    vx = fmaf(a[h], f.x, vx);
                    vy = fmaf(a[h], f.y, vy);
                }
                acc2[r].x += vx;
                acc2[r].y += vy;
            }
        }
        if (tid == 0) {
            float sa = 0.f;
            #pragma unroll
            for (int h = 0; h < HH; h++) sa += a[h];
            oc0 = fmaf(sa, af_in[sn * AFS + 0], oc0);
            oc1 = fmaf(sa, af_in[sn * AFS + 1], oc1);
        }
    }

    // epilogue: af_out (+ fp16 A operand when another GEMM follows)
    const int Kn = 2 + copyw + C;
    __half* Ah = g_Ah + (size_t)n * Kp_next;
    #pragma unroll
    for (int r = 0; r < 2; r++) {
        int p = tid + r * 128;
        if (p < P) {
            int c = 2 * p;
            float v0 = seluf(acc2[r].x * 0.125f + bias[c]);
            float v1 = seluf(acc2[r].y * 0.125f + bias[c + 1]);
            int k0 = 2 + copyw + c;
            af_out[n * AFS + k0] = v0;
            af_out[n * AFS + k0 + 1] = v1;
            if (Kp_next)
                *(__half2*)&Ah[k0] = __floats2half2_rn(v0, v1);
        }
    }
    if (tid < copyw) {
        float v = af_in[n * AFS + tid];
        af_out[n * AFS + 2 + tid] = v;
        if (Kp_next) Ah[2 + tid] = __float2half_rn(v);
    }
    if (tid < Kp_next - Kn)
        Ah[Kn + tid] = __float2half_rn(0.f);
    if (tid == 0) {
        float a0 = af_in[n * AFS + 0], a1 = af_in[n * AFS + 1];
        float c0 = (a0 == 0.f) ? 0.f : ((a0 == 1.f) ? 1.f : oc0 * (0.2f * 0.125f));
        float c1 = (a1 == 1.f) ? 1.f : ((a1 == 0.f) ? 0.f : oc1 * (0.2f * 0.125f));
        af_out[n * AFS + 0] = c0;
        af_out[n * AFS + 1] = c1;
        if (Kp_next)
            *(__half2*)&Ah[0] = __floats2half2_rn(c0, c1);
    }
}

// ---------------- final layer ----------------
__global__ void k_final(int sel, float* __restrict__ out) {
    int n = blockIdx.x;
    int lane = threadIdx.x;
    const float* af_in = g_af[sel];
    int beg = g_rowptr[n], end = g_rowptr[n + 1];
    float oc0 = 0.f, oc1 = 0.f;
    for (int s = beg + lane; s < end; s += 32) {
        int sn = g_srcS[s];
        float sa = 0.f;
        #pragma unroll
        for (int h = 0; h < HH; h++) sa += g_alpha[s * HH + h];
        oc0 = fmaf(sa, af_in[sn * AFS + 0], oc0);
        oc1 = fmaf(sa, af_in[sn * AFS + 1], oc1);
    }
    #pragma unroll
    for (int off = 16; off > 0; off >>= 1) {
        oc0 += __shfl_xor_sync(0xFFFFFFFFu, oc0, off);
        oc1 += __shfl_xor_sync(0xFFFFFFFFu, oc1, off);
    }
    if (lane == 0) {
        float a0 = af_in[n * AFS + 0], a1 = af_in[n * AFS + 1];
        float c0 = (a0 == 0.f) ? 0.f : ((a0 == 1.f) ? 1.f : oc0 * (0.2f * 0.125f));
        float c1 = (a1 == 1.f) ? 1.f : ((a1 == 0.f) ? 0.f : oc1 * (0.2f * 0.125f));
        out[n * 2 + 0] = c0;
        out[n * 2 + 1] = c1;
    }
}

// ---------------- launch ----------------
extern "C" void kernel_launch(void* const* d_in, const int* in_sizes, int n_in,
                              void* d_out, int out_size) {
    const float* data = (const float*)d_in[0];
    const int* eidx = (const int*)d_in[1];
    const float* W0 = (const float*)d_in[2];
    const float* b0 = (const float*)d_in[3];
    const float *W[4], *As[4], *Ad[4], *Bi[4];
    for (int i = 0; i < 4; i++) {
        W[i]  = (const float*)d_in[4 + 4 * i];
        As[i] = (const float*)d_in[5 + 4 * i];
        Ad[i] = (const float*)d_in[6 + 4 * i];
        Bi[i] = (const float*)d_in[7 + 4 * i];
    }
    float* out = (float*)d_out;

    cudaFuncSetAttribute(k_mma_sync, cudaFuncAttributeMaxDynamicSharedMemorySize, SMEM_MMA);

    const int Kd[4]  = {258, 516, 262, 136};
    const int Kpd[4] = {272, 528, 272, 144};
    const int Cd[4]  = {512, 256, 128, 20};

    // layer0 (+convA1 +CSR-init), convB1, foldW, then GEMM1 in the ncu capture slot
    k_layer0f<<<NN, 256>>>(data, W0, b0);
    {
        int Npad = HH * Cd[0];
        dim3 gb((Kpd[0] + 31) / 32, Npad / 32);
        k_convB<<<gb, dim3(32, 8)>>>(W[0], Kd[0], HH * Cd[0], Kpd[0], Npad);
    }
    k_foldW<<<5, 256>>>(W[3], As[3], Ad[3]);
    {
        int Npad = HH * Cd[0];
        dim3 gg(Npad / 128, (NN + 127) / 128);
        k_mma_sync<<<gg, 256, SMEM_MMA>>>(Kpd[0], NN, HH * Cd[0], As[0], Ad[0]);
    }
    k_count<<<(EP + 255) / 256, 256>>>(eidx);
    k_scan<<<1, 1024>>>();
    k_scatter<<<(EP + 255) / 256, 256>>>(eidx);

    int sel = 0;
    for (int l = 0; l < 3; l++) {
        int Nc = HH * Cd[l];
        int Kp = Kpd[l];
        if (l > 0) {
            dim3 gb((Kp + 31) / 32, Nc / 32);
            k_convB<<<gb, dim3(32, 8)>>>(W[l], Kd[l], Nc, Kp, Nc);
            dim3 gg(Nc / 128, (NN + 127) / 128);
            k_mma_sync<<<gg, 256, SMEM_MMA>>>(Kp, NN, Nc, As[l], Ad[l]);
        }
        k_softmax<<<(NN + 7) / 8, 256>>>();
        int Kp_next = (l < 2) ? Kpd[l + 1] : 0;   // no GEMM after layer-3 aggregation
        k_aggf<<<NN, 128>>>(sel, Bi[l], Cd[l], 2 * l + 2, Kp_next);
        sel ^= 1;
    }
    // layer 4: folded scores -> softmax -> coords
    k_scores4<<<(NN + 31) / 32, 256>>>(sel);
    k_softmax<<<(NN + 7) / 8, 256>>>();
    k_final<<<NN, 32>>>(sel, out);
}